// round 5
// baseline (speedup 1.0000x reference)
#include <cuda_runtime.h>
#include <math.h>

// Problem constants
#define T_STEPS 2048
#define BATCH   32
#define DIM     1024
#define BD      (BATCH*DIM)              // 32768
#define OUT_H_OFF 67108864ull            // T*B*D
#define G_CTAS  128
#define SPEC_CTAS 32

// ---------------- device scratch (no allocations allowed) ----------------
__device__ float g_Wx[67108864];   // Wx_all [T,B,D] (256 MB)
__device__ float g_u[DIM];
__device__ float g_v[DIM];
__device__ float g_t1[DIM];
__device__ float g_part[SPEC_CTAS];
__device__ float g_scale;          // 0.99/(sigma+eps)
__device__ unsigned int g_bar2;    // grid barrier counter (spectral)
__device__ unsigned int g_flags[G_CTAS * 32];  // per-CTA step flags, 128B stride

// ---------------- packed fp32x2 FMA (FFMA2, double-rate fp32 on sm_103a) ----
union F2U { float2 f; unsigned long long u; };
union F4U { float4 v; float2 p[2]; };

__device__ __forceinline__ float2 ffma2(float2 a, float2 b, float2 c) {
    F2U ua, ub, uc, ud; ua.f = a; ub.f = b; uc.f = c;
    asm("fma.rn.f32x2 %0, %1, %2, %3;"
        : "=l"(ud.u) : "l"(ua.u), "l"(ub.u), "l"(uc.u));
    return ud.f;
}
__device__ __forceinline__ float2 dup2(float a) {
    F2U r;
    asm("mov.b64 %0, {%1, %1};" : "=l"(r.u) : "f"(a));
    return r.f;
}

// ---------------- resets ----------------
__global__ void k_resetA() {               // 128 threads: zero recurrence flags
    g_flags[threadIdx.x * 32] = 0u;
}
__global__ void k_resetB() { g_bar2 = 0u; }

// ---------------- fused spectral norm (32 CTAs, grid spin barriers) --------
__global__ void __launch_bounds__(256) k_spectral(const float* __restrict__ W,
                                                  const float* __restrict__ u0) {
    __shared__ float red[32];
    __shared__ float s32[32];
    __shared__ float sA[8][32];
    const int tid = threadIdx.x;
    const int cta = blockIdx.x;
    int ph = 0;

#define GBAR() do {                                                        \
        ph++;                                                              \
        __threadfence();                                                   \
        __syncthreads();                                                   \
        if (tid == 0) {                                                    \
            atomicAdd(&g_bar2, 1u);                                        \
            while (*(volatile unsigned*)&g_bar2 < (unsigned)ph * SPEC_CTAS) { } \
            __threadfence();                                               \
        }                                                                  \
        __syncthreads();                                                   \
    } while (0)

    // Phase A: u = u0 / ||u0||  (no eps, per reference). Redundant per CTA.
    {
        float s = 0.f;
        #pragma unroll
        for (int r = 0; r < 4; r++) { float v = u0[r * 256 + tid]; s = fmaf(v, v, s); }
        #pragma unroll
        for (int o = 16; o; o >>= 1) s += __shfl_xor_sync(0xffffffffu, s, o);
        if ((tid & 31) == 0) red[tid >> 5] = s;
        __syncthreads();
        float tot = 0.f;
        #pragma unroll
        for (int r = 0; r < 8; r++) tot += red[r];
        float inv = 1.0f / sqrtf(tot);
        if (tid < 32) g_u[cta * 32 + tid] = u0[cta * 32 + tid] * inv;
    }
    GBAR();

    for (int it = 0; it < 3; it++) {
        // Phase B: v_raw[j] = sum_i W[i][j] * u[i]; CTA owns j-slice of 32
        {
            const int tx = tid & 31, ty = tid >> 5;
            const int j = cta * 32 + tx;
            float acc = 0.f;
            for (int i = ty; i < DIM; i += 8)
                acc = fmaf(W[(size_t)i * DIM + j], g_u[i], acc);
            __syncthreads();
            sA[ty][tx] = acc;
            __syncthreads();
            if (ty == 0) {
                float v = 0.f;
                #pragma unroll
                for (int r = 0; r < 8; r++) v += sA[r][tx];
                g_v[j] = v;
                float sq = v * v;
                #pragma unroll
                for (int o = 16; o; o >>= 1) sq += __shfl_xor_sync(0xffffffffu, sq, o);
                if (tx == 0) g_part[cta] = sq;
            }
        }
        GBAR();
        // Phase C: normalize v in place (own slice), deterministic partial sum
        {
            float s = 0.f;
            #pragma unroll
            for (int c = 0; c < SPEC_CTAS; c++) s += g_part[c];
            float nrm = sqrtf(s) + 1e-8f;
            if (tid < 32) g_v[cta * 32 + tid] /= nrm;
        }
        GBAR();
        // Phase D: t1[i] = sum_j W[i][j] * v[j]; CTA owns i-slice of 32
        {
            const int r8 = tid >> 3, l8 = tid & 7;
            const int row = cta * 32 + r8;
            const float* wr = W + (size_t)row * DIM;
            float acc = 0.f;
            for (int j = l8; j < DIM; j += 8)
                acc = fmaf(wr[j], g_v[j], acc);
            #pragma unroll
            for (int o = 4; o; o >>= 1) acc += __shfl_xor_sync(0xffffffffu, acc, o);
            __syncthreads();
            if (l8 == 0) { s32[r8] = acc; g_t1[row] = acc; }
            __syncthreads();
            if (tid < 32) {
                float v = s32[tid];
                float sq = v * v;
                #pragma unroll
                for (int o = 16; o; o >>= 1) sq += __shfl_xor_sync(0xffffffffu, sq, o);
                if (tid == 0) g_part[cta] = sq;
            }
        }
        GBAR();
        // Phase E: u = t1 / (||t1|| + eps)
        {
            float s = 0.f;
            #pragma unroll
            for (int c = 0; c < SPEC_CTAS; c++) s += g_part[c];
            float nrm = sqrtf(s) + 1e-8f;
            if (tid < 32) g_u[cta * 32 + tid] = g_t1[cta * 32 + tid] / nrm;
        }
        GBAR();
    }
    // Phase F: sigma = |u . t1|
    {
        if (tid < 32) {
            float d = g_u[cta * 32 + tid] * g_t1[cta * 32 + tid];
            #pragma unroll
            for (int o = 16; o; o >>= 1) d += __shfl_xor_sync(0xffffffffu, d, o);
            if (tid == 0) g_part[cta] = d;
        }
    }
    GBAR();
    if (cta == 0 && tid == 0) {
        float s = 0.f;
        #pragma unroll
        for (int c = 0; c < SPEC_CTAS; c++) s += g_part[c];
        g_scale = 0.99f / (fabsf(s) + 1e-8f);
    }
#undef GBAR
}

// ---------------- big GEMM: Wx[m][n] = sum_k X[m][k]*W_x[n][k] ----------------
// 128x128x16 tile, 256 threads, 8x8 register tile, FFMA2 paired over n
__global__ void __launch_bounds__(256) k_gemm(const float* __restrict__ X,
                                              const float* __restrict__ Wm,
                                              float* __restrict__ C) {
    __shared__ float As[16][128];
    __shared__ float Bs[16][128];
    const int bm = blockIdx.y * 128;
    const int bn = blockIdx.x * 128;
    const int tid = threadIdx.x;
    const int tx = tid & 15, ty = tid >> 4;
    float2 acc[8][4];
    #pragma unroll
    for (int i = 0; i < 8; i++)
        #pragma unroll
        for (int j = 0; j < 4; j++) acc[i][j] = make_float2(0.f, 0.f);

    for (int k0 = 0; k0 < DIM; k0 += 16) {
        #pragma unroll
        for (int l = 0; l < 2; l++) {
            int idx = l * 256 + tid;            // float4 index, 512 total
            int r = idx >> 2;
            int c = (idx & 3) << 2;
            float4 a = *(const float4*)(X + (size_t)(bm + r) * DIM + k0 + c);
            As[c + 0][r] = a.x; As[c + 1][r] = a.y; As[c + 2][r] = a.z; As[c + 3][r] = a.w;
            float4 b = *(const float4*)(Wm + (size_t)(bn + r) * DIM + k0 + c);
            Bs[c + 0][r] = b.x; Bs[c + 1][r] = b.y; Bs[c + 2][r] = b.z; Bs[c + 3][r] = b.w;
        }
        __syncthreads();
        #pragma unroll
        for (int k = 0; k < 16; k++) {
            F4U a0, a1, b0, b1;
            a0.v = *(const float4*)&As[k][ty * 8];
            a1.v = *(const float4*)&As[k][ty * 8 + 4];
            b0.v = *(const float4*)&Bs[k][tx * 8];
            b1.v = *(const float4*)&Bs[k][tx * 8 + 4];
            float ra[8] = {a0.v.x, a0.v.y, a0.v.z, a0.v.w, a1.v.x, a1.v.y, a1.v.z, a1.v.w};
            float2 bp[4] = {b0.p[0], b0.p[1], b1.p[0], b1.p[1]};
            #pragma unroll
            for (int i = 0; i < 8; i++) {
                float2 ad = dup2(ra[i]);
                #pragma unroll
                for (int jp = 0; jp < 4; jp++)
                    acc[i][jp] = ffma2(ad, bp[jp], acc[i][jp]);
            }
        }
        __syncthreads();
    }
    #pragma unroll
    for (int i = 0; i < 8; i++) {
        float* cp = C + (size_t)(bm + ty * 8 + i) * DIM + bn + tx * 8;
        F4U lo, hi;
        lo.p[0] = acc[i][0]; lo.p[1] = acc[i][1];
        hi.p[0] = acc[i][2]; hi.p[1] = acc[i][3];
        *(float4*)cp       = lo.v;
        *(float4*)(cp + 4) = hi.v;
    }
}

// ---------------- misc ----------------
__global__ void k_copy_h0(const float* __restrict__ h0, float* __restrict__ out) {
    int i = blockIdx.x * blockDim.x + threadIdx.x;
    if (i < BD) out[OUT_H_OFF + i] = h0[i];
}

// ---------------- persistent recurrence ----------------
// 128 CTAs = 4 batch-groups x 32 e-chunks. Batch-groups are fully independent
// (the recurrence is per-batch), so each group of 32 CTAs syncs only among
// itself via a distributed flag array (one 128B-strided flag per CTA, 32
// parallel pollers) — no contended atomics, no cross-group coupling.
__global__ void __launch_bounds__(256, 1) k_recur(const float* __restrict__ W_h,
                                                  const float* __restrict__ bias,
                                                  const float* __restrict__ bgate,
                                                  float* __restrict__ out) {
    extern __shared__ float sm[];
    float* Wsm = sm;              // 32768 floats (32 e-rows x 1024)
    float* hs  = sm + 32768;      // 8448 floats: h tile (8192) / psum (256*33)

    const int tid = threadIdx.x;
    const int cta = blockIdx.x;
    const int e0 = (cta & 31) << 5;
    const int b0 = (cta >> 5) << 3;
    const int dg = tid & 31;
    const int eg = tid >> 5;
    const int e_l = tid & 31;
    const int b_l = tid >> 5;
    const int grp_base = cta & ~31;          // first CTA of my batch-group

    const float scale = g_scale;
    {   // load + scale W_h slice
        const float4* src = (const float4*)(W_h + (size_t)e0 * DIM);
        float4* dst = (float4*)Wsm;
        #pragma unroll 4
        for (int i = 0; i < 32; i++) {
            float4 w = src[i * 256 + tid];
            w.x *= scale; w.y *= scale; w.z *= scale; w.w *= scale;
            dst[i * 256 + tid] = w;
        }
    }
    const float be = bias[e0 + e_l];
    const float bg = bgate[e0 + e_l];
    float* hout = out + OUT_H_OFF;
    const size_t sliceoff = (size_t)(b0 + b_l) * DIM + e0 + e_l;
    volatile unsigned* myflag = &g_flags[cta * 32];
    volatile unsigned* peerflag = &g_flags[(grp_base + dg) * 32];
    __syncthreads();

    for (int t = 0; t < T_STEPS; t++) {
        const size_t tb = (size_t)t * BD;
        float wxv = g_Wx[tb + sliceoff];             // prefetch early (indep of h)
        {   // load h_prev[b0..b0+7][:] into SMEM
            const float4* hsrc = (const float4*)(hout + tb + (size_t)b0 * DIM);
            float4* hdst = (float4*)hs;
            #pragma unroll
            for (int i = 0; i < 8; i++) hdst[i * 256 + tid] = hsrc[i * 256 + tid];
        }
        __syncthreads();

        float2 acc[8][4];
        #pragma unroll
        for (int b2 = 0; b2 < 8; b2++)
            #pragma unroll
            for (int j = 0; j < 4; j++) acc[b2][j] = make_float2(0.f, 0.f);

        const float4* hs4 = (const float4*)hs;
        const float4* W4  = (const float4*)Wsm;
        #pragma unroll
        for (int i = 0; i < 8; i++) {
            const int base = i * 32 + dg;            // lane==dg -> conflict-free
            F4U w0, w1, w2, w3;
            w0.v = W4[(eg * 4 + 0) * 256 + base];
            w1.v = W4[(eg * 4 + 1) * 256 + base];
            w2.v = W4[(eg * 4 + 2) * 256 + base];
            w3.v = W4[(eg * 4 + 3) * 256 + base];
            #pragma unroll
            for (int b2 = 0; b2 < 8; b2++) {
                F4U h; h.v = hs4[b2 * 256 + base];
                acc[b2][0] = ffma2(h.p[0], w0.p[0], acc[b2][0]);
                acc[b2][0] = ffma2(h.p[1], w0.p[1], acc[b2][0]);
                acc[b2][1] = ffma2(h.p[0], w1.p[0], acc[b2][1]);
                acc[b2][1] = ffma2(h.p[1], w1.p[1], acc[b2][1]);
                acc[b2][2] = ffma2(h.p[0], w2.p[0], acc[b2][2]);
                acc[b2][2] = ffma2(h.p[1], w2.p[1], acc[b2][2]);
                acc[b2][3] = ffma2(h.p[0], w3.p[0], acc[b2][3]);
                acc[b2][3] = ffma2(h.p[1], w3.p[1], acc[b2][3]);
            }
        }
        __syncthreads();                              // hs about to be reused as psum

        #pragma unroll
        for (int b2 = 0; b2 < 8; b2++)
            #pragma unroll
            for (int j = 0; j < 4; j++)
                hs[(b2 * 32 + eg * 4 + j) * 33 + dg] = acc[b2][j].x + acc[b2][j].y;
        __syncthreads();

        float s = 0.f;
        #pragma unroll
        for (int i = 0; i < 32; i++) s += hs[tid * 33 + i];

        // epilogue: thread owns output (b_l, e_l)
        float raw = wxv + s + be;
        float hn = tanhf(raw);
        float gx = wxv + hn + bg;
        float ov = hn * gx / (1.0f + expf(-gx));      // hn * silu(gx)
        out[tb + sliceoff] = ov;
        hout[tb + BD + sliceoff] = hn;

        if (t < T_STEPS - 1) {
            __threadfence();                          // make h stores GPU-visible
            __syncthreads();                          // all threads done + fenced
            if (tid == 0) *myflag = (unsigned)(t + 1);
            if (tid < 32) {                           // 32 lanes poll 32 flags
                while (*peerflag < (unsigned)(t + 1)) { }
            }
            __threadfence();                          // acquire before reading h
            __syncthreads();
        }
    }
}

// ---------------- launch ----------------
extern "C" void kernel_launch(void* const* d_in, const int* in_sizes, int n_in,
                              void* d_out, int out_size) {
    const float* x      = (const float*)d_in[0];
    // d_in[1] = z, unused by the gate_mode=0 reference
    const float* h0     = (const float*)d_in[2];
    const float* W_x    = (const float*)d_in[3];
    const float* W_h    = (const float*)d_in[4];
    const float* b      = (const float*)d_in[5];
    const float* b_gate = (const float*)d_in[6];
    const float* u0     = (const float*)d_in[7];
    float* out = (float*)d_out;

    float* p_Wx;
    cudaGetSymbolAddress((void**)&p_Wx, g_Wx);

    // Profiled launch = my idx 3 (two harness launches precede; ncu -s 5).
    // Put k_gemm there this round to learn the GEMM/recur split + FFMA2 status.
    k_resetA<<<1, 128>>>();                           // idx 0 (zero flags)
    k_resetB<<<1, 1>>>();                             // idx 1
    k_spectral<<<SPEC_CTAS, 256>>>(W_h, u0);          // idx 2
    k_gemm<<<dim3(8, 512), 256>>>(x, W_x, p_Wx);      // idx 3  <-- ncu target
    k_copy_h0<<<(BD + 255) / 256, 256>>>(h0, out);    // idx 4

    const int smem_bytes = (32768 + 8448) * 4;        // 164864
    cudaFuncSetAttribute(k_recur, cudaFuncAttributeMaxDynamicSharedMemorySize, smem_bytes);
    k_recur<<<G_CTAS, 256, smem_bytes>>>(W_h, b, b_gate, out);  // idx 5
}

// round 6
// speedup vs baseline: 1.1906x; 1.1906x over previous
#include <cuda_runtime.h>
#include <math.h>

// Problem constants
#define T_STEPS 2048
#define BATCH   32
#define DIM     1024
#define BD      (BATCH*DIM)              // 32768
#define OUT_H_OFF 67108864ull            // T*B*D
#define G_CTAS  128
#define SPEC_CTAS 32

// ---------------- device scratch (no allocations allowed) ----------------
__device__ float g_Wx[67108864];   // Wx_all [T,B,D] (256 MB)
__device__ float g_u[DIM];
__device__ float g_v[DIM];
__device__ float g_t1[DIM];
__device__ float g_part[SPEC_CTAS];
__device__ float g_scale;          // 0.99/(sigma+eps)
__device__ unsigned int g_bar2;    // grid barrier counter (spectral)
__device__ unsigned int g_cnt[4 * 32];  // per-batch-group step counters (128B apart)

// ---------------- packed fp32x2 FMA (FFMA2, double-rate fp32 on sm_103a) ----
union F2U { float2 f; unsigned long long u; };
union F4U { float4 v; float2 p[2]; };

__device__ __forceinline__ float2 ffma2(float2 a, float2 b, float2 c) {
    F2U ua, ub, uc, ud; ua.f = a; ub.f = b; uc.f = c;
    asm("fma.rn.f32x2 %0, %1, %2, %3;"
        : "=l"(ud.u) : "l"(ua.u), "l"(ub.u), "l"(uc.u));
    return ud.f;
}
__device__ __forceinline__ float2 dup2(float a) {
    F2U r;
    asm("mov.b64 %0, {%1, %1};" : "=l"(r.u) : "f"(a));
    return r.f;
}

// ---------------- resets ----------------
__global__ void k_resetA() {               // zero the 4 group counters
    if (threadIdx.x < 4) g_cnt[threadIdx.x * 32] = 0u;
}
__global__ void k_resetB() { g_bar2 = 0u; }

// ---------------- fused spectral norm (32 CTAs, grid spin barriers) --------
__global__ void __launch_bounds__(256) k_spectral(const float* __restrict__ W,
                                                  const float* __restrict__ u0) {
    __shared__ float red[32];
    __shared__ float s32[32];
    __shared__ float sA[8][32];
    const int tid = threadIdx.x;
    const int cta = blockIdx.x;
    int ph = 0;

#define GBAR() do {                                                        \
        ph++;                                                              \
        __threadfence();                                                   \
        __syncthreads();                                                   \
        if (tid == 0) {                                                    \
            atomicAdd(&g_bar2, 1u);                                        \
            while (*(volatile unsigned*)&g_bar2 < (unsigned)ph * SPEC_CTAS) { } \
            __threadfence();                                               \
        }                                                                  \
        __syncthreads();                                                   \
    } while (0)

    // Phase A: u = u0 / ||u0||  (no eps, per reference). Redundant per CTA.
    {
        float s = 0.f;
        #pragma unroll
        for (int r = 0; r < 4; r++) { float v = u0[r * 256 + tid]; s = fmaf(v, v, s); }
        #pragma unroll
        for (int o = 16; o; o >>= 1) s += __shfl_xor_sync(0xffffffffu, s, o);
        if ((tid & 31) == 0) red[tid >> 5] = s;
        __syncthreads();
        float tot = 0.f;
        #pragma unroll
        for (int r = 0; r < 8; r++) tot += red[r];
        float inv = 1.0f / sqrtf(tot);
        if (tid < 32) g_u[cta * 32 + tid] = u0[cta * 32 + tid] * inv;
    }
    GBAR();

    for (int it = 0; it < 3; it++) {
        // Phase B: v_raw[j] = sum_i W[i][j] * u[i]; CTA owns j-slice of 32
        {
            const int tx = tid & 31, ty = tid >> 5;
            const int j = cta * 32 + tx;
            float acc = 0.f;
            for (int i = ty; i < DIM; i += 8)
                acc = fmaf(W[(size_t)i * DIM + j], g_u[i], acc);
            __syncthreads();
            sA[ty][tx] = acc;
            __syncthreads();
            if (ty == 0) {
                float v = 0.f;
                #pragma unroll
                for (int r = 0; r < 8; r++) v += sA[r][tx];
                g_v[j] = v;
                float sq = v * v;
                #pragma unroll
                for (int o = 16; o; o >>= 1) sq += __shfl_xor_sync(0xffffffffu, sq, o);
                if (tx == 0) g_part[cta] = sq;
            }
        }
        GBAR();
        // Phase C: normalize v in place (own slice), deterministic partial sum
        {
            float s = 0.f;
            #pragma unroll
            for (int c = 0; c < SPEC_CTAS; c++) s += g_part[c];
            float nrm = sqrtf(s) + 1e-8f;
            if (tid < 32) g_v[cta * 32 + tid] /= nrm;
        }
        GBAR();
        // Phase D: t1[i] = sum_j W[i][j] * v[j]; CTA owns i-slice of 32
        {
            const int r8 = tid >> 3, l8 = tid & 7;
            const int row = cta * 32 + r8;
            const float* wr = W + (size_t)row * DIM;
            float acc = 0.f;
            for (int j = l8; j < DIM; j += 8)
                acc = fmaf(wr[j], g_v[j], acc);
            #pragma unroll
            for (int o = 4; o; o >>= 1) acc += __shfl_xor_sync(0xffffffffu, acc, o);
            __syncthreads();
            if (l8 == 0) { s32[r8] = acc; g_t1[row] = acc; }
            __syncthreads();
            if (tid < 32) {
                float v = s32[tid];
                float sq = v * v;
                #pragma unroll
                for (int o = 16; o; o >>= 1) sq += __shfl_xor_sync(0xffffffffu, sq, o);
                if (tid == 0) g_part[cta] = sq;
            }
        }
        GBAR();
        // Phase E: u = t1 / (||t1|| + eps)
        {
            float s = 0.f;
            #pragma unroll
            for (int c = 0; c < SPEC_CTAS; c++) s += g_part[c];
            float nrm = sqrtf(s) + 1e-8f;
            if (tid < 32) g_u[cta * 32 + tid] = g_t1[cta * 32 + tid] / nrm;
        }
        GBAR();
    }
    // Phase F: sigma = |u . t1|
    {
        if (tid < 32) {
            float d = g_u[cta * 32 + tid] * g_t1[cta * 32 + tid];
            #pragma unroll
            for (int o = 16; o; o >>= 1) d += __shfl_xor_sync(0xffffffffu, d, o);
            if (tid == 0) g_part[cta] = d;
        }
    }
    GBAR();
    if (cta == 0 && tid == 0) {
        float s = 0.f;
        #pragma unroll
        for (int c = 0; c < SPEC_CTAS; c++) s += g_part[c];
        g_scale = 0.99f / (fabsf(s) + 1e-8f);
    }
#undef GBAR
}

// ---------------- big GEMM: Wx[m][n] = sum_k X[m][k]*W_x[n][k] ----------------
// 128x128x16 tile, 256 threads, 8x8 register tile, FFMA2 paired over n
__global__ void __launch_bounds__(256) k_gemm(const float* __restrict__ X,
                                              const float* __restrict__ Wm,
                                              float* __restrict__ C) {
    __shared__ float As[16][128];
    __shared__ float Bs[16][128];
    const int bm = blockIdx.y * 128;
    const int bn = blockIdx.x * 128;
    const int tid = threadIdx.x;
    const int tx = tid & 15, ty = tid >> 4;
    float2 acc[8][4];
    #pragma unroll
    for (int i = 0; i < 8; i++)
        #pragma unroll
        for (int j = 0; j < 4; j++) acc[i][j] = make_float2(0.f, 0.f);

    for (int k0 = 0; k0 < DIM; k0 += 16) {
        #pragma unroll
        for (int l = 0; l < 2; l++) {
            int idx = l * 256 + tid;            // float4 index, 512 total
            int r = idx >> 2;
            int c = (idx & 3) << 2;
            float4 a = *(const float4*)(X + (size_t)(bm + r) * DIM + k0 + c);
            As[c + 0][r] = a.x; As[c + 1][r] = a.y; As[c + 2][r] = a.z; As[c + 3][r] = a.w;
            float4 b = *(const float4*)(Wm + (size_t)(bn + r) * DIM + k0 + c);
            Bs[c + 0][r] = b.x; Bs[c + 1][r] = b.y; Bs[c + 2][r] = b.z; Bs[c + 3][r] = b.w;
        }
        __syncthreads();
        #pragma unroll
        for (int k = 0; k < 16; k++) {
            F4U a0, a1, b0, b1;
            a0.v = *(const float4*)&As[k][ty * 8];
            a1.v = *(const float4*)&As[k][ty * 8 + 4];
            b0.v = *(const float4*)&Bs[k][tx * 8];
            b1.v = *(const float4*)&Bs[k][tx * 8 + 4];
            float ra[8] = {a0.v.x, a0.v.y, a0.v.z, a0.v.w, a1.v.x, a1.v.y, a1.v.z, a1.v.w};
            float2 bp[4] = {b0.p[0], b0.p[1], b1.p[0], b1.p[1]};
            #pragma unroll
            for (int i = 0; i < 8; i++) {
                float2 ad = dup2(ra[i]);
                #pragma unroll
                for (int jp = 0; jp < 4; jp++)
                    acc[i][jp] = ffma2(ad, bp[jp], acc[i][jp]);
            }
        }
        __syncthreads();
    }
    #pragma unroll
    for (int i = 0; i < 8; i++) {
        float* cp = C + (size_t)(bm + ty * 8 + i) * DIM + bn + tx * 8;
        F4U lo, hi;
        lo.p[0] = acc[i][0]; lo.p[1] = acc[i][1];
        hi.p[0] = acc[i][2]; hi.p[1] = acc[i][3];
        *(float4*)cp       = lo.v;
        *(float4*)(cp + 4) = hi.v;
    }
}

// ---------------- misc ----------------
__global__ void k_copy_h0(const float* __restrict__ h0, float* __restrict__ out) {
    int i = blockIdx.x * blockDim.x + threadIdx.x;
    if (i < BD) out[OUT_H_OFF + i] = h0[i];
}

// ---------------- persistent recurrence ----------------
// 128 CTAs = 4 batch-groups x 32 e-chunks. W_h_n slice lives in REGISTERS
// (4 e-rows x 8 x float4 = 128 regs/thread, loaded once) — SMEM holds only the
// h tile / psum (34KB). Sync: per-group atomic counter + single-word poll.
__global__ void __launch_bounds__(256, 1) k_recur(const float* __restrict__ W_h,
                                                  const float* __restrict__ bias,
                                                  const float* __restrict__ bgate,
                                                  float* __restrict__ out) {
    __shared__ float hs[8448];    // h tile (8192 floats), psum (8448) aliased after

    const int tid = threadIdx.x;
    const int cta = blockIdx.x;
    const int e0 = (cta & 31) << 5;
    const int b0 = (cta >> 5) << 3;
    const int dg = tid & 31;
    const int eg = tid >> 5;
    const int e_l = tid & 31;
    const int b_l = tid >> 5;
    const int grp = cta >> 5;

    const float scale = g_scale;
    // W regs: rows e0+eg*4+e, float4 at d = i*128 + dg*4  (coalesced loads)
    float4 w[4][8];
    #pragma unroll
    for (int e = 0; e < 4; e++)
        #pragma unroll
        for (int i = 0; i < 8; i++) {
            float4 t = *(const float4*)(W_h + (size_t)(e0 + eg * 4 + e) * DIM + i * 128 + dg * 4);
            t.x *= scale; t.y *= scale; t.z *= scale; t.w *= scale;
            w[e][i] = t;
        }

    const float be = bias[e0 + e_l];
    const float bg = bgate[e0 + e_l];
    float* hout = out + OUT_H_OFF;
    const size_t sliceoff = (size_t)(b0 + b_l) * DIM + e0 + e_l;
    volatile unsigned* cnt = &g_cnt[grp * 32];
    __syncthreads();

    for (int t = 0; t < T_STEPS; t++) {
        const size_t tb = (size_t)t * BD;
        float wxv = g_Wx[tb + sliceoff];             // prefetch (indep of h)
        {   // stage h_prev[b0..b0+7][:] into SMEM
            const float4* hsrc = (const float4*)(hout + tb + (size_t)b0 * DIM);
            float4* hdst = (float4*)hs;
            #pragma unroll
            for (int i = 0; i < 8; i++) hdst[i * 256 + tid] = hsrc[i * 256 + tid];
        }
        __syncthreads();

        float2 acc[8][4];
        #pragma unroll
        for (int b2 = 0; b2 < 8; b2++)
            #pragma unroll
            for (int e = 0; e < 4; e++) acc[b2][e] = make_float2(0.f, 0.f);

        const float4* hs4 = (const float4*)hs;
        #pragma unroll
        for (int i = 0; i < 8; i++) {
            const int base = i * 32 + dg;            // lane==dg -> conflict-free
            #pragma unroll
            for (int b2 = 0; b2 < 8; b2++) {
                F4U h; h.v = hs4[b2 * 256 + base];
                #pragma unroll
                for (int e = 0; e < 4; e++) {
                    F4U wv; wv.v = w[e][i];
                    acc[b2][e] = ffma2(h.p[0], wv.p[0], acc[b2][e]);
                    acc[b2][e] = ffma2(h.p[1], wv.p[1], acc[b2][e]);
                }
            }
        }
        __syncthreads();                              // hs about to be reused as psum

        #pragma unroll
        for (int b2 = 0; b2 < 8; b2++)
            #pragma unroll
            for (int e = 0; e < 4; e++)
                hs[(b2 * 32 + eg * 4 + e) * 33 + dg] = acc[b2][e].x + acc[b2][e].y;
        __syncthreads();

        float s = 0.f;
        #pragma unroll
        for (int i = 0; i < 32; i++) s += hs[tid * 33 + i];

        // epilogue: thread owns output (b_l, e_l)
        float raw = wxv + s + be;
        float hn = tanhf(raw);
        float gx = wxv + hn + bg;
        float ov = hn * gx / (1.0f + expf(-gx));      // hn * silu(gx)
        out[tb + sliceoff] = ov;
        hout[tb + BD + sliceoff] = hn;

        if (t < T_STEPS - 1) {
            __threadfence();                          // h stores -> GPU-visible
            __syncthreads();
            if (tid == 0) {
                atomicAdd((unsigned*)cnt, 1u);
                const unsigned target = 32u * (unsigned)(t + 1);
                while (*cnt < target) { }             // single-line poll
            }
            __syncthreads();                          // broadcast arrival
            // no acquire fence needed: next step reads FRESH addresses (h[t+1]
            // region) never previously cached on this SM
        }
    }
}

// ---------------- launch ----------------
extern "C" void kernel_launch(void* const* d_in, const int* in_sizes, int n_in,
                              void* d_out, int out_size) {
    const float* x      = (const float*)d_in[0];
    // d_in[1] = z, unused by the gate_mode=0 reference
    const float* h0     = (const float*)d_in[2];
    const float* W_x    = (const float*)d_in[3];
    const float* W_h    = (const float*)d_in[4];
    const float* b      = (const float*)d_in[5];
    const float* b_gate = (const float*)d_in[6];
    const float* u0     = (const float*)d_in[7];
    float* out = (float*)d_out;

    float* p_Wx;
    cudaGetSymbolAddress((void**)&p_Wx, g_Wx);

    // Profiled launch = my idx 3 (ncu -s 5 with two harness launches first).
    k_resetA<<<1, 32>>>();                            // idx 0 (zero counters)
    k_resetB<<<1, 1>>>();                             // idx 1
    k_spectral<<<SPEC_CTAS, 256>>>(W_h, u0);          // idx 2
    k_gemm<<<dim3(8, 512), 256>>>(x, W_x, p_Wx);      // idx 3  <-- ncu target
    k_copy_h0<<<(BD + 255) / 256, 256>>>(h0, out);    // idx 4

    k_recur<<<G_CTAS, 256>>>(W_h, b, b_gate, out);    // idx 5
}

// round 7
// speedup vs baseline: 1.1930x; 1.0020x over previous
#include <cuda_runtime.h>
#include <math.h>

// Problem constants
#define T_STEPS 2048
#define BATCH   32
#define DIM     1024
#define BD      (BATCH*DIM)              // 32768
#define OUT_H_OFF 67108864ull            // T*B*D
#define G_CTAS  128
#define SPEC_CTAS 32

// ---------------- device scratch (no allocations allowed) ----------------
__device__ float g_Wx[67108864];   // Wx_all [T,B,D] (256 MB)
__device__ float g_u[DIM];
__device__ float g_v[DIM];
__device__ float g_t1[DIM];
__device__ float g_part[SPEC_CTAS];
__device__ float g_scale;          // 0.99/(sigma+eps)
__device__ unsigned int g_bar2;    // grid barrier counter (spectral)
__device__ unsigned int g_cnt[4 * 32];  // per-batch-group step counters (128B apart)

// ---------------- packed fp32x2 FMA (FFMA2, double-rate fp32 on sm_103a) ----
union F2U { float2 f; unsigned long long u; };
union F4U { float4 v; float2 p[2]; };

__device__ __forceinline__ float2 ffma2(float2 a, float2 b, float2 c) {
    F2U ua, ub, uc, ud; ua.f = a; ub.f = b; uc.f = c;
    asm("fma.rn.f32x2 %0, %1, %2, %3;"
        : "=l"(ud.u) : "l"(ua.u), "l"(ub.u), "l"(uc.u));
    return ud.f;
}

// release/acquire sync primitives (no per-thread MEMBAR, no atomic return wait)
__device__ __forceinline__ void red_release_add(unsigned* p, unsigned v) {
    asm volatile("red.release.gpu.global.add.u32 [%0], %1;" :: "l"(p), "r"(v) : "memory");
}
__device__ __forceinline__ unsigned ld_acquire(const unsigned* p) {
    unsigned v;
    asm volatile("ld.acquire.gpu.global.u32 %0, [%1];" : "=r"(v) : "l"(p) : "memory");
    return v;
}

// ---------------- reset (single launch) ----------------
__global__ void k_reset() {
    if (threadIdx.x < 4) g_cnt[threadIdx.x * 32] = 0u;
    if (threadIdx.x == 127) g_bar2 = 0u;
}

// ---------------- fused spectral norm (32 CTAs, grid spin barriers) --------
// Also copies h0 -> out[OUT_H_OFF] (8192 threads x 1 float4).
__global__ void __launch_bounds__(256) k_spectral(const float* __restrict__ W,
                                                  const float* __restrict__ u0,
                                                  const float* __restrict__ h0,
                                                  float* __restrict__ out) {
    __shared__ float red[32];
    __shared__ float s32[32];
    __shared__ float sA[8][32];
    const int tid = threadIdx.x;
    const int cta = blockIdx.x;
    int ph = 0;

    {   // h0 copy (independent of all phases)
        const int gi = cta * 256 + tid;
        ((float4*)(out + OUT_H_OFF))[gi] = ((const float4*)h0)[gi];
    }

#define GBAR() do {                                                        \
        ph++;                                                              \
        __threadfence();                                                   \
        __syncthreads();                                                   \
        if (tid == 0) {                                                    \
            atomicAdd(&g_bar2, 1u);                                        \
            while (*(volatile unsigned*)&g_bar2 < (unsigned)ph * SPEC_CTAS) { } \
            __threadfence();                                               \
        }                                                                  \
        __syncthreads();                                                   \
    } while (0)

    // Phase A: u = u0 / ||u0||  (no eps, per reference). Redundant per CTA.
    {
        float s = 0.f;
        #pragma unroll
        for (int r = 0; r < 4; r++) { float v = u0[r * 256 + tid]; s = fmaf(v, v, s); }
        #pragma unroll
        for (int o = 16; o; o >>= 1) s += __shfl_xor_sync(0xffffffffu, s, o);
        if ((tid & 31) == 0) red[tid >> 5] = s;
        __syncthreads();
        float tot = 0.f;
        #pragma unroll
        for (int r = 0; r < 8; r++) tot += red[r];
        float inv = 1.0f / sqrtf(tot);
        if (tid < 32) g_u[cta * 32 + tid] = u0[cta * 32 + tid] * inv;
    }
    GBAR();

    for (int it = 0; it < 3; it++) {
        // Phase B: v_raw[j] = sum_i W[i][j] * u[i]; CTA owns j-slice of 32
        {
            const int tx = tid & 31, ty = tid >> 5;
            const int j = cta * 32 + tx;
            float acc = 0.f;
            for (int i = ty; i < DIM; i += 8)
                acc = fmaf(W[(size_t)i * DIM + j], g_u[i], acc);
            __syncthreads();
            sA[ty][tx] = acc;
            __syncthreads();
            if (ty == 0) {
                float v = 0.f;
                #pragma unroll
                for (int r = 0; r < 8; r++) v += sA[r][tx];
                g_v[j] = v;
                float sq = v * v;
                #pragma unroll
                for (int o = 16; o; o >>= 1) sq += __shfl_xor_sync(0xffffffffu, sq, o);
                if (tx == 0) g_part[cta] = sq;
            }
        }
        GBAR();
        // Phase C: normalize v in place (own slice), deterministic partial sum
        {
            float s = 0.f;
            #pragma unroll
            for (int c = 0; c < SPEC_CTAS; c++) s += g_part[c];
            float nrm = sqrtf(s) + 1e-8f;
            if (tid < 32) g_v[cta * 32 + tid] /= nrm;
        }
        GBAR();
        // Phase D: t1[i] = sum_j W[i][j] * v[j]; CTA owns i-slice of 32
        {
            const int r8 = tid >> 3, l8 = tid & 7;
            const int row = cta * 32 + r8;
            const float* wr = W + (size_t)row * DIM;
            float acc = 0.f;
            for (int j = l8; j < DIM; j += 8)
                acc = fmaf(wr[j], g_v[j], acc);
            #pragma unroll
            for (int o = 4; o; o >>= 1) acc += __shfl_xor_sync(0xffffffffu, acc, o);
            __syncthreads();
            if (l8 == 0) { s32[r8] = acc; g_t1[row] = acc; }
            __syncthreads();
            if (tid < 32) {
                float v = s32[tid];
                float sq = v * v;
                #pragma unroll
                for (int o = 16; o; o >>= 1) sq += __shfl_xor_sync(0xffffffffu, sq, o);
                if (tid == 0) g_part[cta] = sq;
            }
        }
        GBAR();
        // Phase E: u = t1 / (||t1|| + eps)
        {
            float s = 0.f;
            #pragma unroll
            for (int c = 0; c < SPEC_CTAS; c++) s += g_part[c];
            float nrm = sqrtf(s) + 1e-8f;
            if (tid < 32) g_u[cta * 32 + tid] = g_t1[cta * 32 + tid] / nrm;
        }
        GBAR();
    }
    // Phase F: sigma = |u . t1|
    {
        if (tid < 32) {
            float d = g_u[cta * 32 + tid] * g_t1[cta * 32 + tid];
            #pragma unroll
            for (int o = 16; o; o >>= 1) d += __shfl_xor_sync(0xffffffffu, d, o);
            if (tid == 0) g_part[cta] = d;
        }
    }
    GBAR();
    if (cta == 0 && tid == 0) {
        float s = 0.f;
        #pragma unroll
        for (int c = 0; c < SPEC_CTAS; c++) s += g_part[c];
        g_scale = 0.99f / (fabsf(s) + 1e-8f);
    }
#undef GBAR
}

// ---------------- big GEMM: Wx[m][n] = sum_k X[m][k]*W_x[n][k] ----------------
// 128x128x16 tile, 256 threads, 8x8 register tile, FFMA2 paired over n
__global__ void __launch_bounds__(256) k_gemm(const float* __restrict__ X,
                                              const float* __restrict__ Wm,
                                              float* __restrict__ C) {
    __shared__ float As[16][128];
    __shared__ float Bs[16][128];
    const int bm = blockIdx.y * 128;
    const int bn = blockIdx.x * 128;
    const int tid = threadIdx.x;
    const int tx = tid & 15, ty = tid >> 4;
    float2 acc[8][4];
    #pragma unroll
    for (int i = 0; i < 8; i++)
        #pragma unroll
        for (int j = 0; j < 4; j++) acc[i][j] = make_float2(0.f, 0.f);

    for (int k0 = 0; k0 < DIM; k0 += 16) {
        #pragma unroll
        for (int l = 0; l < 2; l++) {
            int idx = l * 256 + tid;            // float4 index, 512 total
            int r = idx >> 2;
            int c = (idx & 3) << 2;
            float4 a = *(const float4*)(X + (size_t)(bm + r) * DIM + k0 + c);
            As[c + 0][r] = a.x; As[c + 1][r] = a.y; As[c + 2][r] = a.z; As[c + 3][r] = a.w;
            float4 b = *(const float4*)(Wm + (size_t)(bn + r) * DIM + k0 + c);
            Bs[c + 0][r] = b.x; Bs[c + 1][r] = b.y; Bs[c + 2][r] = b.z; Bs[c + 3][r] = b.w;
        }
        __syncthreads();
        #pragma unroll
        for (int k = 0; k < 16; k++) {
            F4U a0, a1, b0, b1;
            a0.v = *(const float4*)&As[k][ty * 8];
            a1.v = *(const float4*)&As[k][ty * 8 + 4];
            b0.v = *(const float4*)&Bs[k][tx * 8];
            b1.v = *(const float4*)&Bs[k][tx * 8 + 4];
            float ra[8] = {a0.v.x, a0.v.y, a0.v.z, a0.v.w, a1.v.x, a1.v.y, a1.v.z, a1.v.w};
            float2 bp[4] = {b0.p[0], b0.p[1], b1.p[0], b1.p[1]};
            #pragma unroll
            for (int i = 0; i < 8; i++) {
                F2U ad; asm("mov.b64 %0, {%1, %1};" : "=l"(ad.u) : "f"(ra[i]));
                #pragma unroll
                for (int jp = 0; jp < 4; jp++)
                    acc[i][jp] = ffma2(ad.f, bp[jp], acc[i][jp]);
            }
        }
        __syncthreads();
    }
    #pragma unroll
    for (int i = 0; i < 8; i++) {
        float* cp = C + (size_t)(bm + ty * 8 + i) * DIM + bn + tx * 8;
        F4U lo, hi;
        lo.p[0] = acc[i][0]; lo.p[1] = acc[i][1];
        hi.p[0] = acc[i][2]; hi.p[1] = acc[i][3];
        *(float4*)cp       = lo.v;
        *(float4*)(cp + 4) = hi.v;
    }
}

// ---------------- persistent recurrence ----------------
// 128 CTAs = 4 batch-groups x 32 e-chunks. W_h_n slice in REGISTERS (128/thr).
// Sync: publish h early (before silu epilogue), CTA-sync + tid0 red.release
// arrive, tid0 ld.acquire poll. No per-thread MEMBAR anywhere.
__global__ void __launch_bounds__(256, 1) k_recur(const float* __restrict__ W_h,
                                                  const float* __restrict__ bias,
                                                  const float* __restrict__ bgate,
                                                  float* __restrict__ out) {
    __shared__ float hs[8448];    // h tile (8192 floats) / psum (8448) aliased

    const int tid = threadIdx.x;
    const int cta = blockIdx.x;
    const int e0 = (cta & 31) << 5;
    const int b0 = (cta >> 5) << 3;
    const int dg = tid & 31;
    const int eg = tid >> 5;
    const int e_l = tid & 31;
    const int b_l = tid >> 5;
    const int grp = cta >> 5;

    const float scale = g_scale;
    // W regs: rows e0+eg*4+e, float4 at d = i*128 + dg*4  (coalesced loads)
    float4 w[4][8];
    #pragma unroll
    for (int e = 0; e < 4; e++)
        #pragma unroll
        for (int i = 0; i < 8; i++) {
            float4 t = *(const float4*)(W_h + (size_t)(e0 + eg * 4 + e) * DIM + i * 128 + dg * 4);
            t.x *= scale; t.y *= scale; t.z *= scale; t.w *= scale;
            w[e][i] = t;
        }

    const float be = bias[e0 + e_l];
    const float bg = bgate[e0 + e_l];
    float* hout = out + OUT_H_OFF;
    const size_t sliceoff = (size_t)(b0 + b_l) * DIM + e0 + e_l;
    unsigned* cnt = &g_cnt[grp * 32];
    __syncthreads();

    for (int t = 0; t < T_STEPS; t++) {
        const size_t tb = (size_t)t * BD;
        float wxv = g_Wx[tb + sliceoff];             // prefetch (indep of h)
        {   // stage h_prev[b0..b0+7][:] into SMEM
            const float4* hsrc = (const float4*)(hout + tb + (size_t)b0 * DIM);
            float4* hdst = (float4*)hs;
            #pragma unroll
            for (int i = 0; i < 8; i++) hdst[i * 256 + tid] = hsrc[i * 256 + tid];
        }
        __syncthreads();

        float2 acc[8][4];
        #pragma unroll
        for (int b2 = 0; b2 < 8; b2++)
            #pragma unroll
            for (int e = 0; e < 4; e++) acc[b2][e] = make_float2(0.f, 0.f);

        const float4* hs4 = (const float4*)hs;
        #pragma unroll
        for (int i = 0; i < 8; i++) {
            const int base = i * 32 + dg;            // lane==dg -> conflict-free
            #pragma unroll
            for (int b2 = 0; b2 < 8; b2++) {
                F4U h; h.v = hs4[b2 * 256 + base];
                #pragma unroll
                for (int e = 0; e < 4; e++) {
                    F4U wv; wv.v = w[e][i];
                    acc[b2][e] = ffma2(h.p[0], wv.p[0], acc[b2][e]);
                    acc[b2][e] = ffma2(h.p[1], wv.p[1], acc[b2][e]);
                }
            }
        }
        __syncthreads();                              // hs about to be reused as psum

        #pragma unroll
        for (int b2 = 0; b2 < 8; b2++)
            #pragma unroll
            for (int e = 0; e < 4; e++)
                hs[(b2 * 32 + eg * 4 + e) * 33 + dg] = acc[b2][e].x + acc[b2][e].y;
        __syncthreads();

        float s = 0.f;
        #pragma unroll
        for (int i = 0; i < 32; i++) s += hs[tid * 33 + i];

        // ---- critical path: h_new publish + arrive FIRST ----
        float raw = wxv + s + be;
        float hn = tanhf(raw);
        hout[tb + BD + sliceoff] = hn;                // publish h[t+1]
        __syncthreads();                              // all h stores issued (CTA HB)
        if (tid == 0) red_release_add(cnt, 1u);       // gpu-scope release arrive

        // ---- off-path epilogue overlaps peers' arrival ----
        float gx = wxv + hn + bg;
        float ov = hn * gx / (1.0f + expf(-gx));      // hn * silu(gx)
        out[tb + sliceoff] = ov;

        if (t < T_STEPS - 1) {
            if (tid == 0) {
                const unsigned target = 32u * (unsigned)(t + 1);
                while (ld_acquire(cnt) < target) { }  // acquire poll
            }
            __syncthreads();                          // broadcast arrival
        }
    }
}

// ---------------- launch ----------------
extern "C" void kernel_launch(void* const* d_in, const int* in_sizes, int n_in,
                              void* d_out, int out_size) {
    const float* x      = (const float*)d_in[0];
    // d_in[1] = z, unused by the gate_mode=0 reference
    const float* h0     = (const float*)d_in[2];
    const float* W_x    = (const float*)d_in[3];
    const float* W_h    = (const float*)d_in[4];
    const float* b      = (const float*)d_in[5];
    const float* b_gate = (const float*)d_in[6];
    const float* u0     = (const float*)d_in[7];
    float* out = (float*)d_out;

    float* p_Wx;
    cudaGetSymbolAddress((void**)&p_Wx, g_Wx);

    // Profiled launch = my idx 3 (2 harness launches + ncu -s 5).
    // This round: k_recur sits there — the kernel we need to see.
    k_reset<<<1, 128>>>();                                 // idx 0
    k_spectral<<<SPEC_CTAS, 256>>>(W_h, u0, h0, out);      // idx 1 (+h0 copy)
    k_gemm<<<dim3(8, 512), 256>>>(x, W_x, p_Wx);           // idx 2
    k_recur<<<G_CTAS, 256>>>(W_h, b, b_gate, out);         // idx 3  <-- ncu target
}

// round 8
// speedup vs baseline: 1.2580x; 1.0545x over previous
#include <cuda_runtime.h>
#include <math.h>

// Problem constants
#define T_STEPS 2048
#define BATCH   32
#define DIM     1024
#define BD      (BATCH*DIM)              // 32768
#define OUT_H_OFF 67108864ull            // T*B*D
#define G_CTAS  128
#define SPEC_CTAS 32

// ---------------- device scratch (no allocations allowed) ----------------
__device__ float g_Wx[67108864];   // Wx_all [T,B,D] (256 MB)
__device__ float g_u[DIM];
__device__ float g_v[DIM];
__device__ float g_t1[DIM];
__device__ float g_part[SPEC_CTAS];
__device__ float g_scale;          // 0.99/(sigma+eps)
__device__ unsigned int g_bar2;    // grid barrier counter (spectral)
__device__ unsigned int g_cnt[4 * 32];  // per-batch-group step counters (128B apart)

// ---------------- packed fp32x2 FMA (FFMA2, double-rate fp32 on sm_103a) ----
union F2U { float2 f; unsigned long long u; };
union F4U { float4 v; float2 p[2]; };

__device__ __forceinline__ float2 ffma2(float2 a, float2 b, float2 c) {
    F2U ua, ub, uc, ud; ua.f = a; ub.f = b; uc.f = c;
    asm("fma.rn.f32x2 %0, %1, %2, %3;"
        : "=l"(ud.u) : "l"(ua.u), "l"(ub.u), "l"(uc.u));
    return ud.f;
}

// release/acquire sync primitives
__device__ __forceinline__ void red_release_add(unsigned* p, unsigned v) {
    asm volatile("red.release.gpu.global.add.u32 [%0], %1;" :: "l"(p), "r"(v) : "memory");
}
__device__ __forceinline__ unsigned ld_acquire(const unsigned* p) {
    unsigned v;
    asm volatile("ld.acquire.gpu.global.u32 %0, [%1];" : "=r"(v) : "l"(p) : "memory");
    return v;
}

// ---------------- reset (single launch) ----------------
__global__ void k_reset() {
    if (threadIdx.x < 4) g_cnt[threadIdx.x * 32] = 0u;
    if (threadIdx.x == 127) g_bar2 = 0u;
}

// ---------------- fused spectral norm (32 CTAs, grid spin barriers) --------
// Also copies h0 -> out[OUT_H_OFF].
__global__ void __launch_bounds__(256) k_spectral(const float* __restrict__ W,
                                                  const float* __restrict__ u0,
                                                  const float* __restrict__ h0,
                                                  float* __restrict__ out) {
    __shared__ float red[32];
    __shared__ float s32[32];
    __shared__ float sA[8][32];
    const int tid = threadIdx.x;
    const int cta = blockIdx.x;
    int ph = 0;

    {   // h0 copy
        const int gi = cta * 256 + tid;
        ((float4*)(out + OUT_H_OFF))[gi] = ((const float4*)h0)[gi];
    }

#define GBAR() do {                                                        \
        ph++;                                                              \
        __threadfence();                                                   \
        __syncthreads();                                                   \
        if (tid == 0) {                                                    \
            atomicAdd(&g_bar2, 1u);                                        \
            while (*(volatile unsigned*)&g_bar2 < (unsigned)ph * SPEC_CTAS) { } \
            __threadfence();                                               \
        }                                                                  \
        __syncthreads();                                                   \
    } while (0)

    {   // u = u0 / ||u0||
        float s = 0.f;
        #pragma unroll
        for (int r = 0; r < 4; r++) { float v = u0[r * 256 + tid]; s = fmaf(v, v, s); }
        #pragma unroll
        for (int o = 16; o; o >>= 1) s += __shfl_xor_sync(0xffffffffu, s, o);
        if ((tid & 31) == 0) red[tid >> 5] = s;
        __syncthreads();
        float tot = 0.f;
        #pragma unroll
        for (int r = 0; r < 8; r++) tot += red[r];
        float inv = 1.0f / sqrtf(tot);
        if (tid < 32) g_u[cta * 32 + tid] = u0[cta * 32 + tid] * inv;
    }
    GBAR();

    for (int it = 0; it < 3; it++) {
        {   // v_raw[j] = sum_i W[i][j]*u[i]
            const int tx = tid & 31, ty = tid >> 5;
            const int j = cta * 32 + tx;
            float acc = 0.f;
            for (int i = ty; i < DIM; i += 8)
                acc = fmaf(W[(size_t)i * DIM + j], g_u[i], acc);
            __syncthreads();
            sA[ty][tx] = acc;
            __syncthreads();
            if (ty == 0) {
                float v = 0.f;
                #pragma unroll
                for (int r = 0; r < 8; r++) v += sA[r][tx];
                g_v[j] = v;
                float sq = v * v;
                #pragma unroll
                for (int o = 16; o; o >>= 1) sq += __shfl_xor_sync(0xffffffffu, sq, o);
                if (tx == 0) g_part[cta] = sq;
            }
        }
        GBAR();
        {   // normalize v
            float s = 0.f;
            #pragma unroll
            for (int c = 0; c < SPEC_CTAS; c++) s += g_part[c];
            float nrm = sqrtf(s) + 1e-8f;
            if (tid < 32) g_v[cta * 32 + tid] /= nrm;
        }
        GBAR();
        {   // t1[i] = sum_j W[i][j]*v[j]
            const int r8 = tid >> 3, l8 = tid & 7;
            const int row = cta * 32 + r8;
            const float* wr = W + (size_t)row * DIM;
            float acc = 0.f;
            for (int j = l8; j < DIM; j += 8)
                acc = fmaf(wr[j], g_v[j], acc);
            #pragma unroll
            for (int o = 4; o; o >>= 1) acc += __shfl_xor_sync(0xffffffffu, acc, o);
            __syncthreads();
            if (l8 == 0) { s32[r8] = acc; g_t1[row] = acc; }
            __syncthreads();
            if (tid < 32) {
                float v = s32[tid];
                float sq = v * v;
                #pragma unroll
                for (int o = 16; o; o >>= 1) sq += __shfl_xor_sync(0xffffffffu, sq, o);
                if (tid == 0) g_part[cta] = sq;
            }
        }
        GBAR();
        {   // u = t1 / (||t1|| + eps)
            float s = 0.f;
            #pragma unroll
            for (int c = 0; c < SPEC_CTAS; c++) s += g_part[c];
            float nrm = sqrtf(s) + 1e-8f;
            if (tid < 32) g_u[cta * 32 + tid] = g_t1[cta * 32 + tid] / nrm;
        }
        GBAR();
    }
    {   // sigma = |u . t1|
        if (tid < 32) {
            float d = g_u[cta * 32 + tid] * g_t1[cta * 32 + tid];
            #pragma unroll
            for (int o = 16; o; o >>= 1) d += __shfl_xor_sync(0xffffffffu, d, o);
            if (tid == 0) g_part[cta] = d;
        }
    }
    GBAR();
    if (cta == 0 && tid == 0) {
        float s = 0.f;
        #pragma unroll
        for (int c = 0; c < SPEC_CTAS; c++) s += g_part[c];
        g_scale = 0.99f / (fabsf(s) + 1e-8f);
    }
#undef GBAR
}

// ---------------- big GEMM: Wx[m][n] = sum_k X[m][k]*W_x[n][k] ----------------
// 128x128x16 tile, 128 threads, 8m x 16n register tile, FFMA2 over n,
// double-buffered global staging. LDS per k per thread: 96B for 128 FMA.
__global__ void __launch_bounds__(128) k_gemm(const float* __restrict__ X,
                                              const float* __restrict__ Wm,
                                              float* __restrict__ C) {
    __shared__ float As[16][128];
    __shared__ float Bs[16][128];
    const int bm = blockIdx.y * 128;
    const int bn = blockIdx.x * 128;
    const int tid = threadIdx.x;
    const int tx = tid & 7;        // n-group (8)
    const int ty = tid >> 3;       // m-group (16)

    float2 acc[8][8];
    #pragma unroll
    for (int i = 0; i < 8; i++)
        #pragma unroll
        for (int j = 0; j < 8; j++) acc[i][j] = make_float2(0.f, 0.f);

    // stage indices: 512 f4 per matrix, 4 per thread per matrix
    // idx = l*128 + tid : r = idx>>2 (row 0..127), c4 = idx&3 (f4-col)
    float4 ra[4], rb[4];
    #pragma unroll
    for (int l = 0; l < 4; l++) {
        int idx = l * 128 + tid;
        int r = idx >> 2, c = (idx & 3) << 2;
        ra[l] = *(const float4*)(X  + (size_t)(bm + r) * DIM + c);
        rb[l] = *(const float4*)(Wm + (size_t)(bn + r) * DIM + c);
    }

    for (int k0 = 0; k0 < DIM; k0 += 16) {
        #pragma unroll
        for (int l = 0; l < 4; l++) {
            int idx = l * 128 + tid;
            int r = idx >> 2, c = (idx & 3) << 2;
            As[c + 0][r] = ra[l].x; As[c + 1][r] = ra[l].y;
            As[c + 2][r] = ra[l].z; As[c + 3][r] = ra[l].w;
            Bs[c + 0][r] = rb[l].x; Bs[c + 1][r] = rb[l].y;
            Bs[c + 2][r] = rb[l].z; Bs[c + 3][r] = rb[l].w;
        }
        __syncthreads();

        if (k0 + 16 < DIM) {       // prefetch next k-tile
            #pragma unroll
            for (int l = 0; l < 4; l++) {
                int idx = l * 128 + tid;
                int r = idx >> 2, c = (idx & 3) << 2;
                ra[l] = *(const float4*)(X  + (size_t)(bm + r) * DIM + k0 + 16 + c);
                rb[l] = *(const float4*)(Wm + (size_t)(bn + r) * DIM + k0 + 16 + c);
            }
        }

        #pragma unroll
        for (int k = 0; k < 16; k++) {
            F4U a0, a1;
            a0.v = *(const float4*)&As[k][ty * 8];
            a1.v = *(const float4*)&As[k][ty * 8 + 4];
            float am[8] = {a0.v.x, a0.v.y, a0.v.z, a0.v.w, a1.v.x, a1.v.y, a1.v.z, a1.v.w};
            F4U b[4];
            #pragma unroll
            for (int j = 0; j < 4; j++)
                b[j].v = *(const float4*)&Bs[k][tx * 4 + j * 32];
            #pragma unroll
            for (int i = 0; i < 8; i++) {
                F2U ad; asm("mov.b64 %0, {%1, %1};" : "=l"(ad.u) : "f"(am[i]));
                #pragma unroll
                for (int j = 0; j < 4; j++) {
                    acc[i][2 * j]     = ffma2(ad.f, b[j].p[0], acc[i][2 * j]);
                    acc[i][2 * j + 1] = ffma2(ad.f, b[j].p[1], acc[i][2 * j + 1]);
                }
            }
        }
        __syncthreads();
    }
    #pragma unroll
    for (int i = 0; i < 8; i++) {
        float* crow = C + (size_t)(bm + ty * 8 + i) * DIM + bn;
        #pragma unroll
        for (int j = 0; j < 4; j++) {
            F4U o; o.p[0] = acc[i][2 * j]; o.p[1] = acc[i][2 * j + 1];
            *(float4*)(crow + tx * 4 + j * 32) = o.v;
        }
    }
}

// ---------------- persistent recurrence ----------------
// 128 CTAs = 4 batch-groups x 32 e-chunks. W in REGISTERS (128/thread).
// SMEM: h tile and psum in SEPARATE regions (no aliasing syncs).
// Sync per step: all-thread acquire poll + 3 bar.sync + tid0 red.release.
__global__ void __launch_bounds__(256, 1) k_recur(const float* __restrict__ W_h,
                                                  const float* __restrict__ bias,
                                                  const float* __restrict__ bgate,
                                                  float* __restrict__ out) {
    extern __shared__ float sm[];
    float* hs = sm;               // 8192 floats: h tile
    float* ps = sm + 8192;        // 8448 floats: psum (256 x 33)

    const int tid = threadIdx.x;
    const int cta = blockIdx.x;
    const int e0 = (cta & 31) << 5;
    const int b0 = (cta >> 5) << 3;
    const int dg = tid & 31;
    const int eg = tid >> 5;
    const int e_l = tid & 31;
    const int b_l = tid >> 5;
    const int grp = cta >> 5;

    const float scale = g_scale;
    float4 w[4][8];
    #pragma unroll
    for (int e = 0; e < 4; e++)
        #pragma unroll
        for (int i = 0; i < 8; i++) {
            float4 t = *(const float4*)(W_h + (size_t)(e0 + eg * 4 + e) * DIM + i * 128 + dg * 4);
            t.x *= scale; t.y *= scale; t.z *= scale; t.w *= scale;
            w[e][i] = t;
        }

    const float be = bias[e0 + e_l];
    const float bg = bgate[e0 + e_l];
    float* hout = out + OUT_H_OFF;
    const size_t sliceoff = (size_t)(b0 + b_l) * DIM + e0 + e_l;
    unsigned* cnt = &g_cnt[grp * 32];
    __syncthreads();

    for (int t = 0; t < T_STEPS; t++) {
        const size_t tb = (size_t)t * BD;

        if (t) {                                      // all threads poll (1 read/warp)
            const unsigned target = 32u * (unsigned)t;
            while (ld_acquire(cnt) < target) { }
        }

        float wxv = g_Wx[tb + sliceoff];              // prefetch (indep of h)
        {   // stage h_prev[b0..b0+7][:] into SMEM
            const float4* hsrc = (const float4*)(hout + tb + (size_t)b0 * DIM);
            float4* hdst = (float4*)hs;
            #pragma unroll
            for (int i = 0; i < 8; i++) hdst[i * 256 + tid] = hsrc[i * 256 + tid];
        }
        __syncthreads();                              // BAR1: h staged

        float2 acc[8][4];
        #pragma unroll
        for (int b2 = 0; b2 < 8; b2++)
            #pragma unroll
            for (int e = 0; e < 4; e++) acc[b2][e] = make_float2(0.f, 0.f);

        const float4* hs4 = (const float4*)hs;
        #pragma unroll
        for (int i = 0; i < 8; i++) {
            const int base = i * 32 + dg;             // lane==dg -> conflict-free
            #pragma unroll
            for (int b2 = 0; b2 < 8; b2++) {
                F4U h; h.v = hs4[b2 * 256 + base];
                #pragma unroll
                for (int e = 0; e < 4; e++) {
                    F4U wv; wv.v = w[e][i];
                    acc[b2][e] = ffma2(h.p[0], wv.p[0], acc[b2][e]);
                    acc[b2][e] = ffma2(h.p[1], wv.p[1], acc[b2][e]);
                }
            }
        }

        #pragma unroll
        for (int b2 = 0; b2 < 8; b2++)
            #pragma unroll
            for (int e = 0; e < 4; e++)
                ps[(b2 * 32 + eg * 4 + e) * 33 + dg] = acc[b2][e].x + acc[b2][e].y;
        __syncthreads();                              // BAR2: psum ready

        float s = 0.f;
        #pragma unroll
        for (int i = 0; i < 32; i++) s += ps[tid * 33 + i];

        // critical path: h publish + arrive first
        float raw = wxv + s + be;
        float hn = tanhf(raw);
        hout[tb + BD + sliceoff] = hn;                // publish h[t+1]
        __syncthreads();                              // BAR3: all h stores issued
        if (tid == 0) red_release_add(cnt, 1u);       // gpu-scope release arrive

        // off-path epilogue overlaps peers' arrival
        float gx = wxv + hn + bg;
        float ov = hn * gx / (1.0f + expf(-gx));      // hn * silu(gx)
        out[tb + sliceoff] = ov;
    }
}

// ---------------- launch ----------------
extern "C" void kernel_launch(void* const* d_in, const int* in_sizes, int n_in,
                              void* d_out, int out_size) {
    const float* x      = (const float*)d_in[0];
    // d_in[1] = z, unused by the gate_mode=0 reference
    const float* h0     = (const float*)d_in[2];
    const float* W_x    = (const float*)d_in[3];
    const float* W_h    = (const float*)d_in[4];
    const float* b      = (const float*)d_in[5];
    const float* b_gate = (const float*)d_in[6];
    const float* u0     = (const float*)d_in[7];
    float* out = (float*)d_out;

    float* p_Wx;
    cudaGetSymbolAddress((void**)&p_Wx, g_Wx);

    // Profiled launch = my idx 3 (2 harness launches + ncu -s 5) -> k_recur.
    k_reset<<<1, 128>>>();                                 // idx 0
    k_spectral<<<SPEC_CTAS, 256>>>(W_h, u0, h0, out);      // idx 1
    k_gemm<<<dim3(8, 512), 128>>>(x, W_x, p_Wx);           // idx 2
    const int smem_bytes = (8192 + 8448) * 4;              // 66560
    cudaFuncSetAttribute(k_recur, cudaFuncAttributeMaxDynamicSharedMemorySize, smem_bytes);
    k_recur<<<G_CTAS, 256, smem_bytes>>>(W_h, b, b_gate, out);  // idx 3 <-- ncu
}